// round 13
// baseline (speedup 1.0000x reference)
#include <cuda_runtime.h>
#include <cstdint>

#define F      1024
#define F4     256
#define DOMS   8
#define NBLK   296          // 2 CTAs/SM x 148 SMs
#define TPB    256
#define RMAX   256          // rows per block: ceil(65536/296)=222
#define KEEP   76           // rows/block kept L2-resident for norm_k (92 MB total)
#define PF     6            // prefetch distance in 4-row groups (~24 rows ahead)
#define EPSV   1e-5f

// ---------------- scratch (static device globals; no allocation) ----------------
__device__ float g_psum[(size_t)NBLK * DOMS * F];   // 9.7 MB (L2-resident by budget)
__device__ float g_psq [(size_t)NBLK * DOMS * F];   // 9.7 MB
__device__ int   g_pcnt[NBLK * DOMS];
__device__ float g_scale[DOMS * F];
__device__ float g_bias [DOMS * F];

// accumulate float4 vv into (SA,QA)
#define ACC(SA, QA) do { \
    SA.x += vv.x; SA.y += vv.y; SA.z += vv.z; SA.w += vv.w; \
    QA.x = fmaf(vv.x, vv.x, QA.x); QA.y = fmaf(vv.y, vv.y, QA.y); \
    QA.z = fmaf(vv.z, vv.z, QA.z); QA.w = fmaf(vv.w, vv.w, QA.w); } while (0)

#define ACC_SWITCH(D) do { switch (D) { \
    case 0: ACC(sa0, qa0); break; case 1: ACC(sa1, qa1); break; \
    case 2: ACC(sa2, qa2); break; case 3: ACC(sa3, qa3); break; \
    case 4: ACC(sa4, qa4); break; case 5: ACC(sa5, qa5); break; \
    case 6: ACC(sa6, qa6); break; default: ACC(sa7, qa7); break; } } while (0)

// L2 prefetch of group G's 4 rows (this thread's 16B slice)
#define PREF(BASEPTR, G) do { int _rr = (G) * 4; \
    _Pragma("unroll") for (int _i = 0; _i < 4; _i++) \
        asm volatile("prefetch.global.L2 [%0];" :: "l"(BASEPTR + (size_t)(_rr + _i) * F4)); } while (0)

// group loaders: evict-first (streamed) vs default (L2-kept)
#define LOADG_CS(VB, DB, G) do { int _rr = (G) * 4; \
    _Pragma("unroll") for (int _i = 0; _i < 4; _i++) { \
        VB[_i] = __ldcs(xb + (size_t)(_rr + _i) * F4); DB[_i] = ysm[_rr + _i]; } } while (0)

#define LOADG_DF(VB, DB, G) do { int _rr = (G) * 4; \
    _Pragma("unroll") for (int _i = 0; _i < 4; _i++) { \
        VB[_i] = xb[(size_t)(_rr + _i) * F4]; DB[_i] = ysm[_rr + _i]; } } while (0)

#define LOADG_ANY(VB, DB, G) do { \
    if ((G) < cut4) { LOADG_CS(VB, DB, G); } else { LOADG_DF(VB, DB, G); } } while (0)

#define CONSUME(VB, DB) do { \
    _Pragma("unroll") for (int _i = 0; _i < 4; _i++) { \
        float4 vv = VB[_i]; ACC_SWITCH(DB[_i]); } } while (0)

// ---- y dtype detection (int64 vs int32): int64 in [0,8) -> odd words zero ----
__device__ __forceinline__ int detect_is64(const void* yv, int n, int tid) {
    const unsigned* yw = (const unsigned*)yv;
    int lim = min(1024, (n - 1) / 2);
    int t = 0;
    for (int i = tid; i < lim; i += TPB)
        if (yw[2 * i + 1] != 0u) t = 1;
    return __syncthreads_or(t) ? 0 : 1;
}

// ================= K1: stats; pipelined + L2 prefetch; last KEEP rows L2-kept ====
__global__ void __launch_bounds__(TPB, 2) stats_k(
    const float4* __restrict__ x, const void* __restrict__ yv, int n)
{
    __shared__ int ysm[RMAX];
    __shared__ int cnt[DOMS];

    const int tid   = threadIdx.x;
    const int b     = blockIdx.x;
    const int rpb   = (n + NBLK - 1) / NBLK;
    const int base  = b * rpb;
    const int nrows = min(rpb, n - base);

    int is64 = detect_is64(yv, n, tid);

    if (tid < DOMS) cnt[tid] = 0;
    __syncthreads();
    if (tid < nrows) {
        int d = is64 ? (int)((const long long*)yv)[base + tid]
                     : ((const int*)yv)[base + tid];
        ysm[tid] = d;
        atomicAdd(&cnt[d], 1);
    }
    __syncthreads();

    float4 sa0 = {0,0,0,0}, sa1 = {0,0,0,0}, sa2 = {0,0,0,0}, sa3 = {0,0,0,0};
    float4 sa4 = {0,0,0,0}, sa5 = {0,0,0,0}, sa6 = {0,0,0,0}, sa7 = {0,0,0,0};
    float4 qa0 = {0,0,0,0}, qa1 = {0,0,0,0}, qa2 = {0,0,0,0}, qa3 = {0,0,0,0};
    float4 qa4 = {0,0,0,0}, qa5 = {0,0,0,0}, qa6 = {0,0,0,0}, qa7 = {0,0,0,0};

    {
        const float4* xb = x + (size_t)base * F4 + tid;
        const int k    = nrows >> 2;                     // total full 4-row groups
        const int cut4 = max(0, nrows - KEEP) >> 2;      // groups streamed (evict-first)
        float4 vA[4], vB[4]; int dA[4], dB[4];

        if (k > 0) {
            // warm the prefetch window for the first groups
            for (int p = 1; p <= PF && p < k; p++) PREF(xb, p);
            if (PF < k) PREF(xb, PF);
            LOADG_ANY(vA, dA, 0);
            int g = 1;
            for (; g + 1 < k; g += 2) {
                if (g + PF < k) PREF(xb, g + PF);
                LOADG_ANY(vB, dB, g);
                CONSUME(vA, dA);
                if (g + 1 + PF < k) PREF(xb, g + 1 + PF);
                LOADG_ANY(vA, dA, g + 1);
                CONSUME(vB, dB);
            }
            if (g < k) { LOADG_ANY(vB, dB, g); CONSUME(vA, dA); CONSUME(vB, dB); }
            else       { CONSUME(vA, dA); }
        }
        for (int r = k * 4; r < nrows; r++) {            // tail rows (default: kept)
            float4 vv = xb[(size_t)r * F4];
            int d = ysm[r];
            ACC_SWITCH(d);
        }
    }

    // partials: DEFAULT policy -> stay L2-resident for table_k (19.4 MB budget)
    float4* psum = (float4*)(g_psum + (size_t)b * DOMS * F);
    float4* psq  = (float4*)(g_psq  + (size_t)b * DOMS * F);
    psum[0 * F4 + tid] = sa0; psq[0 * F4 + tid] = qa0;
    psum[1 * F4 + tid] = sa1; psq[1 * F4 + tid] = qa1;
    psum[2 * F4 + tid] = sa2; psq[2 * F4 + tid] = qa2;
    psum[3 * F4 + tid] = sa3; psq[3 * F4 + tid] = qa3;
    psum[4 * F4 + tid] = sa4; psq[4 * F4 + tid] = qa4;
    psum[5 * F4 + tid] = sa5; psq[5 * F4 + tid] = qa5;
    psum[6 * F4 + tid] = sa6; psq[6 * F4 + tid] = qa6;
    psum[7 * F4 + tid] = sa7; psq[7 * F4 + tid] = qa7;
    if (tid < DOMS) g_pcnt[b * DOMS + tid] = (nrows > 0) ? cnt[tid] : 0;
}

// ================= K2: distributed partial reduce -> (scale, bias) table =========
__global__ void __launch_bounds__(TPB, 2) table_k(
    const float* __restrict__ gamma, const float* __restrict__ beta)
{
    __shared__ int   scnt[DOMS], cpart[64];
    __shared__ float sred[9][28], qred[9][28];

    const int tid = threadIdx.x;
    const int b   = blockIdx.x;

    if (tid < 64) {
        int d = tid & 7, g = tid >> 3;
        int s0 = g * 37, s1 = min(NBLK, s0 + 37);
        int c = 0;
        for (int sl = s0; sl < s1; sl++) c += g_pcnt[sl * DOMS + d];
        cpart[tid] = c;
    }
    __syncthreads();
    if (tid < DOMS) {
        int c = 0;
        #pragma unroll
        for (int g = 0; g < 8; g++) c += cpart[g * 8 + tid];
        scnt[tid] = c;
    }

    const int start = b * 28;                   // 296*28 >= 8192
    const int p = tid % 28, c = tid / 28;       // c in 0..9 (c==9 idle)
    if (c < 9 && start + p < DOMS * F) {
        int j  = start + p;
        int s0 = c * 33, s1 = min(NBLK, s0 + 33);
        float ss = 0.f, qq = 0.f;
        for (int sl = s0; sl < s1; sl++) {
            ss += g_psum[(size_t)sl * (DOMS * F) + j];   // expect L2 hits
            qq += g_psq [(size_t)sl * (DOMS * F) + j];
        }
        sred[c][p] = ss; qred[c][p] = qq;
    }
    __syncthreads();
    if (tid < 28 && start + tid < DOMS * F) {
        int jj = start + tid;
        float ss = 0.f, qq = 0.f;
        #pragma unroll
        for (int cc = 0; cc < 9; cc++) { ss += sred[cc][tid]; qq += qred[cc][tid]; }
        int d = jj >> 10, f = jj & (F - 1);
        float cf = (float)scnt[d];
        float sc, bi;
        if (cf > 1.f) {
            float inv  = 1.f / cf;
            float mean = ss * inv;
            float var  = fmaxf(qq * inv - mean * mean, 0.f);
            sc = gamma[f] * rsqrtf(var + EPSV);
            bi = fmaf(-mean, sc, beta[f]);
        } else if (cf == 1.f) { sc = 1.f; bi = 0.f; }   // count==1 -> raw x
        else                  { sc = 0.f; bi = 0.f; }   // count==0 -> 0
        g_scale[jj] = sc;
        g_bias [jj] = bi;
    }
}

// ================= K3: normalize, pipelined descending + L2 prefetch ==============
__global__ void __launch_bounds__(TPB, 2) norm_k(
    const float4* __restrict__ x, const void* __restrict__ yv,
    float4* __restrict__ out, int n)
{
    __shared__ int ysm[RMAX];

    const int tid   = threadIdx.x;
    const int b     = blockIdx.x;
    const int rpb   = (n + NBLK - 1) / NBLK;
    const int base  = b * rpb;
    const int nrows = min(rpb, n - base);

    int is64 = detect_is64(yv, n, tid);

    if (tid < nrows)
        ysm[tid] = is64 ? (int)((const long long*)yv)[base + tid]
                        : ((const int*)yv)[base + tid];
    __syncthreads();

    const float4* sc4 = (const float4*)g_scale;
    const float4* bi4 = (const float4*)g_bias;
    const float4* xc  = x   + (size_t)base * F4 + tid;
    float4*       oc  = out + (size_t)base * F4 + tid;

    const int k = nrows >> 2;                       // full 4-row groups

    // tail rows first (descending), so overall order is strictly descending
    for (int r = nrows - 1; r >= k * 4; r--) {
        int d = ysm[r];
        float4 v  = __ldcs(xc + (size_t)r * F4);
        float4 sc = sc4[d * F4 + tid];
        float4 bi = bi4[d * F4 + tid];
        float4 o;
        o.x = fmaf(v.x, sc.x, bi.x);
        o.y = fmaf(v.y, sc.y, bi.y);
        o.z = fmaf(v.z, sc.z, bi.z);
        o.w = fmaf(v.w, sc.w, bi.w);
        __stcs(oc + (size_t)r * F4, o);
    }

#define NLOAD(VB, DB, G) do { int _rr = (G) * 4; \
    _Pragma("unroll") for (int _i = 0; _i < 4; _i++) { \
        VB[_i] = __ldcs(xc + (size_t)(_rr + _i) * F4); DB[_i] = ysm[_rr + _i]; } } while (0)

#define NSTORE(VB, DB, G) do { int _rr = (G) * 4; \
    _Pragma("unroll") for (int _i = 0; _i < 4; _i++) { \
        float4 sc = sc4[DB[_i] * F4 + tid]; \
        float4 bi = bi4[DB[_i] * F4 + tid]; \
        float4 o; \
        o.x = fmaf(VB[_i].x, sc.x, bi.x); \
        o.y = fmaf(VB[_i].y, sc.y, bi.y); \
        o.z = fmaf(VB[_i].z, sc.z, bi.z); \
        o.w = fmaf(VB[_i].w, sc.w, bi.w); \
        __stcs(oc + (size_t)(_rr + _i) * F4, o); } } while (0)

    if (k > 0) {
        float4 vA[4], vB[4]; int dA[4], dB[4];
        for (int p = k - 2; p >= k - 1 - PF && p >= 0; p--) PREF(xc, p);
        NLOAD(vA, dA, k - 1);                       // prologue (highest group)
        int g = k - 2;
        for (; g >= 1; g -= 2) {                    // steady state: load-ahead
            if (g - PF >= 0) PREF(xc, g - PF);
            NLOAD(vB, dB, g);
            NSTORE(vA, dA, g + 1);
            if (g - 1 - PF >= 0) PREF(xc, g - 1 - PF);
            NLOAD(vA, dA, g - 1);
            NSTORE(vB, dB, g);
        }
        if (g == 0) {
            NLOAD(vB, dB, 0);
            NSTORE(vA, dA, 1);
            NSTORE(vB, dB, 0);
        } else {
            NSTORE(vA, dA, 0);
        }
    }
}

// ---------------- launch ----------------
extern "C" void kernel_launch(void* const* d_in, const int* in_sizes, int n_in,
                              void* d_out, int out_size) {
    const float4* x     = (const float4*)d_in[0];
    const void*   y     = d_in[1];
    const float*  gamma = (const float*)d_in[2];
    const float*  beta  = (const float*)d_in[3];
    float4*       out   = (float4*)d_out;

    int n = in_sizes[1];   // batch (y element count)

    stats_k<<<NBLK, TPB>>>(x, y, n);
    table_k<<<NBLK, TPB>>>(gamma, beta);
    norm_k <<<NBLK, TPB>>>(x, y, out, n);
}

// round 14
// speedup vs baseline: 1.0557x; 1.0557x over previous
#include <cuda_runtime.h>
#include <cstdint>

#define F       1024
#define F4      256
#define DOMS    8
#define NBLK    296          // 2 CTAs/SM x 148 SMs
#define TPB     256
#define RMAX    256          // rows per block: ceil(65536/296)=222
#define TROWS   8            // rows per ring stage (32 KB)
#define STAGES  3            // ring depth (96 KB dynamic smem)
#define STBYTES (TROWS * 4096)
#define EPSV    1e-5f

// ---------------- scratch (static device globals; no allocation) ----------------
__device__ float g_psum[(size_t)NBLK * DOMS * F];   // 9.7 MB (L2-resident)
__device__ float g_psq [(size_t)NBLK * DOMS * F];   // 9.7 MB
__device__ int   g_pcnt[NBLK * DOMS];
__device__ float g_scale[DOMS * F];
__device__ float g_bias [DOMS * F];

// ---------------- mbarrier / bulk-copy helpers ----------------
__device__ __forceinline__ uint32_t smem_u32(const void* p) {
    uint32_t a;
    asm("{ .reg .u64 t; cvta.to.shared.u64 t, %1; cvt.u32.u64 %0, t; }"
        : "=r"(a) : "l"(p));
    return a;
}
__device__ __forceinline__ void mbar_init(uint32_t mb, uint32_t cnt) {
    asm volatile("mbarrier.init.shared.b64 [%0], %1;" :: "r"(mb), "r"(cnt) : "memory");
}
__device__ __forceinline__ void mbar_expect_tx(uint32_t mb, uint32_t bytes) {
    asm volatile("mbarrier.arrive.expect_tx.shared.b64 _, [%0], %1;"
                 :: "r"(mb), "r"(bytes) : "memory");
}
__device__ __forceinline__ void bulk_g2s(uint32_t dst, const void* src,
                                         uint32_t bytes, uint32_t mb) {
    asm volatile("cp.async.bulk.shared::cta.global.mbarrier::complete_tx::bytes "
                 "[%0], [%1], %2, [%3];"
                 :: "r"(dst), "l"(src), "r"(bytes), "r"(mb) : "memory");
}
__device__ __forceinline__ void mbar_wait(uint32_t mb, uint32_t parity) {
    uint32_t done;
    asm volatile(
        "{\n\t.reg .pred p;\n\t"
        "mbarrier.try_wait.parity.acquire.cta.shared::cta.b64 p, [%1], %2;\n\t"
        "selp.b32 %0, 1, 0, p;\n\t}"
        : "=r"(done) : "r"(mb), "r"(parity) : "memory");
    if (!done) {
        asm volatile(
            "{\n\t.reg .pred P1;\n\t"
            "WL_%=:\n\t"
            "mbarrier.try_wait.parity.acquire.cta.shared::cta.b64 P1, [%0], %1, 0x989680;\n\t"
            "@P1 bra.uni WD_%=;\n\t"
            "bra.uni WL_%=;\n\t"
            "WD_%=:\n\t}"
            :: "r"(mb), "r"(parity) : "memory");
    }
}

// accumulate float4 vv into (SA,QA)
#define ACC(SA, QA) do { \
    SA.x += vv.x; SA.y += vv.y; SA.z += vv.z; SA.w += vv.w; \
    QA.x = fmaf(vv.x, vv.x, QA.x); QA.y = fmaf(vv.y, vv.y, QA.y); \
    QA.z = fmaf(vv.z, vv.z, QA.z); QA.w = fmaf(vv.w, vv.w, QA.w); } while (0)

#define ACC_SWITCH(D) do { switch (D) { \
    case 0: ACC(sa0, qa0); break; case 1: ACC(sa1, qa1); break; \
    case 2: ACC(sa2, qa2); break; case 3: ACC(sa3, qa3); break; \
    case 4: ACC(sa4, qa4); break; case 5: ACC(sa5, qa5); break; \
    case 6: ACC(sa6, qa6); break; default: ACC(sa7, qa7); break; } } while (0)

// ---- y dtype detection (int64 vs int32): int64 in [0,8) -> odd words zero ----
__device__ __forceinline__ int detect_is64(const void* yv, int n, int tid) {
    const unsigned* yw = (const unsigned*)yv;
    int lim = min(1024, (n - 1) / 2);
    int t = 0;
    for (int i = tid; i < lim; i += TPB)
        if (yw[2 * i + 1] != 0u) t = 1;
    return __syncthreads_or(t) ? 0 : 1;
}

// ================= K1: stats via cp.async.bulk smem ring ==========================
__global__ void __launch_bounds__(TPB, 2) stats_k(
    const float4* __restrict__ x, const void* __restrict__ yv, int n)
{
    extern __shared__ float4 ring[];             // STAGES * TROWS * 256 float4
    __shared__ int ysm[RMAX];
    __shared__ int cnt[DOMS];
    __shared__ __align__(8) unsigned long long mbar_s[STAGES];

    const int tid   = threadIdx.x;
    const int b     = blockIdx.x;
    const int rpb   = (n + NBLK - 1) / NBLK;
    const int base  = b * rpb;
    const int nrows = min(rpb, n - base);

    int is64 = detect_is64(yv, n, tid);

    if (tid < DOMS) cnt[tid] = 0;
    if (tid == 0) {
        #pragma unroll
        for (int s = 0; s < STAGES; s++) mbar_init(smem_u32(&mbar_s[s]), 1u);
    }
    __syncthreads();
    if (tid < nrows) {
        int d = is64 ? (int)((const long long*)yv)[base + tid]
                     : ((const int*)yv)[base + tid];
        ysm[tid] = d;
        atomicAdd(&cnt[d], 1);
    }
    __syncthreads();

    float4 sa0 = {0,0,0,0}, sa1 = {0,0,0,0}, sa2 = {0,0,0,0}, sa3 = {0,0,0,0};
    float4 sa4 = {0,0,0,0}, sa5 = {0,0,0,0}, sa6 = {0,0,0,0}, sa7 = {0,0,0,0};
    float4 qa0 = {0,0,0,0}, qa1 = {0,0,0,0}, qa2 = {0,0,0,0}, qa3 = {0,0,0,0};
    float4 qa4 = {0,0,0,0}, qa5 = {0,0,0,0}, qa6 = {0,0,0,0}, qa7 = {0,0,0,0};

    const char* gsrc = (const char*)(x + (size_t)base * F4);
    const uint32_t ring0 = smem_u32(ring);
    const int nst = (nrows + TROWS - 1) / TROWS;

    // prologue: fill the ring
    if (tid == 0) {
        for (int s = 0; s < STAGES && s < nst; s++) {
            uint32_t bytes = (uint32_t)min(TROWS, nrows - s * TROWS) * 4096u;
            uint32_t mb = smem_u32(&mbar_s[s]);
            mbar_expect_tx(mb, bytes);
            bulk_g2s(ring0 + s * STBYTES, gsrc + (size_t)s * STBYTES, bytes, mb);
        }
    }

    for (int i = 0; i < nst; i++) {
        const int slot = i % STAGES;
        const uint32_t mb = smem_u32(&mbar_s[slot]);
        mbar_wait(mb, (unsigned)(i / STAGES) & 1u);

        const int rows  = min(TROWS, nrows - i * TROWS);
        const int rbase = i * TROWS;
        const float4* bufp = ring + slot * (TROWS * 256) + tid;
        if (rows == TROWS) {
            #pragma unroll
            for (int j = 0; j < TROWS; j++) {
                float4 vv = bufp[j * 256];
                int d = ysm[rbase + j];
                ACC_SWITCH(d);
            }
        } else {
            for (int j = 0; j < rows; j++) {
                float4 vv = bufp[j * 256];
                int d = ysm[rbase + j];
                ACC_SWITCH(d);
            }
        }
        __syncthreads();                         // empty-barrier: all reads done
        const int nxt = i + STAGES;
        if (tid == 0 && nxt < nst) {
            uint32_t bytes = (uint32_t)min(TROWS, nrows - nxt * TROWS) * 4096u;
            mbar_expect_tx(mb, bytes);
            bulk_g2s(ring0 + slot * STBYTES, gsrc + (size_t)nxt * STBYTES, bytes, mb);
        }
    }

    // partials: default policy -> L2-resident for table_k
    float4* psum = (float4*)(g_psum + (size_t)b * DOMS * F);
    float4* psq  = (float4*)(g_psq  + (size_t)b * DOMS * F);
    psum[0 * F4 + tid] = sa0; psq[0 * F4 + tid] = qa0;
    psum[1 * F4 + tid] = sa1; psq[1 * F4 + tid] = qa1;
    psum[2 * F4 + tid] = sa2; psq[2 * F4 + tid] = qa2;
    psum[3 * F4 + tid] = sa3; psq[3 * F4 + tid] = qa3;
    psum[4 * F4 + tid] = sa4; psq[4 * F4 + tid] = qa4;
    psum[5 * F4 + tid] = sa5; psq[5 * F4 + tid] = qa5;
    psum[6 * F4 + tid] = sa6; psq[6 * F4 + tid] = qa6;
    psum[7 * F4 + tid] = sa7; psq[7 * F4 + tid] = qa7;
    if (tid < DOMS) g_pcnt[b * DOMS + tid] = (nrows > 0) ? cnt[tid] : 0;
}

// ================= K2: distributed partial reduce -> (scale, bias) table =========
__global__ void __launch_bounds__(TPB, 2) table_k(
    const float* __restrict__ gamma, const float* __restrict__ beta)
{
    __shared__ int   scnt[DOMS], cpart[64];
    __shared__ float sred[9][28], qred[9][28];

    const int tid = threadIdx.x;
    const int b   = blockIdx.x;

    if (tid < 64) {
        int d = tid & 7, g = tid >> 3;
        int s0 = g * 37, s1 = min(NBLK, s0 + 37);
        int c = 0;
        for (int sl = s0; sl < s1; sl++) c += g_pcnt[sl * DOMS + d];
        cpart[tid] = c;
    }
    __syncthreads();
    if (tid < DOMS) {
        int c = 0;
        #pragma unroll
        for (int g = 0; g < 8; g++) c += cpart[g * 8 + tid];
        scnt[tid] = c;
    }

    const int start = b * 28;                   // 296*28 >= 8192
    const int p = tid % 28, c = tid / 28;       // c in 0..9 (c==9 idle)
    if (c < 9 && start + p < DOMS * F) {
        int j  = start + p;
        int s0 = c * 33, s1 = min(NBLK, s0 + 33);
        float ss = 0.f, qq = 0.f;
        for (int sl = s0; sl < s1; sl++) {
            ss += g_psum[(size_t)sl * (DOMS * F) + j];   // expect L2 hits
            qq += g_psq [(size_t)sl * (DOMS * F) + j];
        }
        sred[c][p] = ss; qred[c][p] = qq;
    }
    __syncthreads();
    if (tid < 28 && start + tid < DOMS * F) {
        int jj = start + tid;
        float ss = 0.f, qq = 0.f;
        #pragma unroll
        for (int cc = 0; cc < 9; cc++) { ss += sred[cc][tid]; qq += qred[cc][tid]; }
        int d = jj >> 10, f = jj & (F - 1);
        float cf = (float)scnt[d];
        float sc, bi;
        if (cf > 1.f) {
            float inv  = 1.f / cf;
            float mean = ss * inv;
            float var  = fmaxf(qq * inv - mean * mean, 0.f);
            sc = gamma[f] * rsqrtf(var + EPSV);
            bi = fmaf(-mean, sc, beta[f]);
        } else if (cf == 1.f) { sc = 1.f; bi = 0.f; }   // count==1 -> raw x
        else                  { sc = 0.f; bi = 0.f; }   // count==0 -> 0
        g_scale[jj] = sc;
        g_bias [jj] = bi;
    }
}

// ================= K3: normalize, pipelined descending stream (R11) ===============
__global__ void __launch_bounds__(TPB, 2) norm_k(
    const float4* __restrict__ x, const void* __restrict__ yv,
    float4* __restrict__ out, int n)
{
    __shared__ int ysm[RMAX];

    const int tid   = threadIdx.x;
    const int b     = blockIdx.x;
    const int rpb   = (n + NBLK - 1) / NBLK;
    const int base  = b * rpb;
    const int nrows = min(rpb, n - base);

    int is64 = detect_is64(yv, n, tid);

    if (tid < nrows)
        ysm[tid] = is64 ? (int)((const long long*)yv)[base + tid]
                        : ((const int*)yv)[base + tid];
    __syncthreads();

    const float4* sc4 = (const float4*)g_scale;
    const float4* bi4 = (const float4*)g_bias;
    const float4* xc  = x   + (size_t)base * F4 + tid;
    float4*       oc  = out + (size_t)base * F4 + tid;

    const int k = nrows >> 2;                       // full 4-row groups

    for (int r = nrows - 1; r >= k * 4; r--) {      // tail first (descending)
        int d = ysm[r];
        float4 v  = __ldcs(xc + (size_t)r * F4);
        float4 sc = sc4[d * F4 + tid];
        float4 bi = bi4[d * F4 + tid];
        float4 o;
        o.x = fmaf(v.x, sc.x, bi.x);
        o.y = fmaf(v.y, sc.y, bi.y);
        o.z = fmaf(v.z, sc.z, bi.z);
        o.w = fmaf(v.w, sc.w, bi.w);
        __stcs(oc + (size_t)r * F4, o);
    }

#define NLOAD(VB, DB, G) do { int _rr = (G) * 4; \
    _Pragma("unroll") for (int _i = 0; _i < 4; _i++) { \
        VB[_i] = __ldcs(xc + (size_t)(_rr + _i) * F4); DB[_i] = ysm[_rr + _i]; } } while (0)

#define NSTORE(VB, DB, G) do { int _rr = (G) * 4; \
    _Pragma("unroll") for (int _i = 0; _i < 4; _i++) { \
        float4 sc = sc4[DB[_i] * F4 + tid]; \
        float4 bi = bi4[DB[_i] * F4 + tid]; \
        float4 o; \
        o.x = fmaf(VB[_i].x, sc.x, bi.x); \
        o.y = fmaf(VB[_i].y, sc.y, bi.y); \
        o.z = fmaf(VB[_i].z, sc.z, bi.z); \
        o.w = fmaf(VB[_i].w, sc.w, bi.w); \
        __stcs(oc + (size_t)(_rr + _i) * F4, o); } } while (0)

    if (k > 0) {
        float4 vA[4], vB[4]; int dA[4], dB[4];
        NLOAD(vA, dA, k - 1);                       // prologue (highest group)
        int g = k - 2;
        for (; g >= 1; g -= 2) {                    // steady state: load-ahead
            NLOAD(vB, dB, g);
            NSTORE(vA, dA, g + 1);
            NLOAD(vA, dA, g - 1);
            NSTORE(vB, dB, g);
        }
        if (g == 0) {
            NLOAD(vB, dB, 0);
            NSTORE(vA, dA, 1);
            NSTORE(vB, dB, 0);
        } else {
            NSTORE(vA, dA, 0);
        }
    }
}

// ---------------- launch ----------------
extern "C" void kernel_launch(void* const* d_in, const int* in_sizes, int n_in,
                              void* d_out, int out_size) {
    const float4* x     = (const float4*)d_in[0];
    const void*   y     = d_in[1];
    const float*  gamma = (const float*)d_in[2];
    const float*  beta  = (const float*)d_in[3];
    float4*       out   = (float4*)d_out;

    int n = in_sizes[1];   // batch (y element count)

    static int smem_set = 0;
    if (!smem_set) {
        cudaFuncSetAttribute(stats_k, cudaFuncAttributeMaxDynamicSharedMemorySize,
                             STAGES * STBYTES);
        smem_set = 1;
    }
    stats_k<<<NBLK, TPB, STAGES * STBYTES>>>(x, y, n);
    table_k<<<NBLK, TPB>>>(gamma, beta);
    norm_k <<<NBLK, TPB>>>(x, y, out, n);
}

// round 15
// speedup vs baseline: 1.0885x; 1.0311x over previous
#include <cuda_runtime.h>
#include <cstdint>

#define F       1024
#define F4      256
#define DOMS    8
#define NBLK    296          // 2 CTAs/SM x 148 SMs
#define TPB     256
#define RMAX    256          // rows per block: ceil(65536/296)=222
#define KEEP    76           // rows/block kept L2-resident for norm_k (92 MB)
#define TROWS   8            // rows per ring stage (32 KB)
#define STAGES  3            // ring depth (96 KB dynamic smem)
#define STBYTES (TROWS * 4096)
#define EPSV    1e-5f

// ---------------- scratch (static device globals; no allocation) ----------------
__device__ float g_psum[(size_t)NBLK * DOMS * F];   // 9.7 MB (L2-resident)
__device__ float g_psq [(size_t)NBLK * DOMS * F];   // 9.7 MB
__device__ int   g_pcnt[NBLK * DOMS];
__device__ float g_scale[DOMS * F];
__device__ float g_bias [DOMS * F];

// ---------------- mbarrier / bulk-copy helpers ----------------
__device__ __forceinline__ uint32_t smem_u32(const void* p) {
    uint32_t a;
    asm("{ .reg .u64 t; cvta.to.shared.u64 t, %1; cvt.u32.u64 %0, t; }"
        : "=r"(a) : "l"(p));
    return a;
}
__device__ __forceinline__ void mbar_init(uint32_t mb, uint32_t cnt) {
    asm volatile("mbarrier.init.shared.b64 [%0], %1;" :: "r"(mb), "r"(cnt) : "memory");
}
__device__ __forceinline__ void mbar_expect_tx(uint32_t mb, uint32_t bytes) {
    asm volatile("mbarrier.arrive.expect_tx.shared.b64 _, [%0], %1;"
                 :: "r"(mb), "r"(bytes) : "memory");
}
__device__ __forceinline__ void bulk_g2s(uint32_t dst, const void* src,
                                         uint32_t bytes, uint32_t mb) {
    asm volatile("cp.async.bulk.shared::cta.global.mbarrier::complete_tx::bytes "
                 "[%0], [%1], %2, [%3];"
                 :: "r"(dst), "l"(src), "r"(bytes), "r"(mb) : "memory");
}
// bulk copy with L2 evict-first policy (streamed region: dead after this read)
__device__ __forceinline__ void bulk_g2s_ef(uint32_t dst, const void* src,
                                            uint32_t bytes, uint32_t mb) {
    unsigned long long pol;
    asm("createpolicy.fractional.L2::evict_first.b64 %0, 1.0;" : "=l"(pol));
    asm volatile("cp.async.bulk.shared::cta.global.mbarrier::complete_tx::bytes"
                 ".L2::cache_hint [%0], [%1], %2, [%3], %4;"
                 :: "r"(dst), "l"(src), "r"(bytes), "r"(mb), "l"(pol) : "memory");
}
__device__ __forceinline__ void mbar_wait(uint32_t mb, uint32_t parity) {
    uint32_t done;
    asm volatile(
        "{\n\t.reg .pred p;\n\t"
        "mbarrier.try_wait.parity.acquire.cta.shared::cta.b64 p, [%1], %2;\n\t"
        "selp.b32 %0, 1, 0, p;\n\t}"
        : "=r"(done) : "r"(mb), "r"(parity) : "memory");
    if (!done) {
        asm volatile(
            "{\n\t.reg .pred P1;\n\t"
            "WL_%=:\n\t"
            "mbarrier.try_wait.parity.acquire.cta.shared::cta.b64 P1, [%0], %1, 0x989680;\n\t"
            "@P1 bra.uni WD_%=;\n\t"
            "bra.uni WL_%=;\n\t"
            "WD_%=:\n\t}"
            :: "r"(mb), "r"(parity) : "memory");
    }
}

// accumulate float4 vv into (SA,QA)
#define ACC(SA, QA) do { \
    SA.x += vv.x; SA.y += vv.y; SA.z += vv.z; SA.w += vv.w; \
    QA.x = fmaf(vv.x, vv.x, QA.x); QA.y = fmaf(vv.y, vv.y, QA.y); \
    QA.z = fmaf(vv.z, vv.z, QA.z); QA.w = fmaf(vv.w, vv.w, QA.w); } while (0)

#define ACC_SWITCH(D) do { switch (D) { \
    case 0: ACC(sa0, qa0); break; case 1: ACC(sa1, qa1); break; \
    case 2: ACC(sa2, qa2); break; case 3: ACC(sa3, qa3); break; \
    case 4: ACC(sa4, qa4); break; case 5: ACC(sa5, qa5); break; \
    case 6: ACC(sa6, qa6); break; default: ACC(sa7, qa7); break; } } while (0)

// ---- y dtype detection (int64 vs int32): int64 in [0,8) -> odd words zero ----
__device__ __forceinline__ int detect_is64(const void* yv, int n, int tid) {
    const unsigned* yw = (const unsigned*)yv;
    int lim = min(1024, (n - 1) / 2);
    int t = 0;
    for (int i = tid; i < lim; i += TPB)
        if (yw[2 * i + 1] != 0u) t = 1;
    return __syncthreads_or(t) ? 0 : 1;
}

// ================= K1: stats via cp.async.bulk ring + L2 policy ===================
__global__ void __launch_bounds__(TPB, 2) stats_k(
    const float4* __restrict__ x, const void* __restrict__ yv, int n)
{
    extern __shared__ float4 ring[];             // STAGES * TROWS * 256 float4
    __shared__ int ysm[RMAX];
    __shared__ int cnt[DOMS];
    __shared__ __align__(8) unsigned long long mbar_s[STAGES];

    const int tid   = threadIdx.x;
    const int b     = blockIdx.x;
    const int rpb   = (n + NBLK - 1) / NBLK;
    const int base  = b * rpb;
    const int nrows = min(rpb, n - base);
    const int cutr  = max(0, nrows - KEEP);      // rows below cutr: evict-first

    int is64 = detect_is64(yv, n, tid);

    if (tid < DOMS) cnt[tid] = 0;
    if (tid == 0) {
        #pragma unroll
        for (int s = 0; s < STAGES; s++) mbar_init(smem_u32(&mbar_s[s]), 1u);
    }
    __syncthreads();
    if (tid < nrows) {
        int d = is64 ? (int)((const long long*)yv)[base + tid]
                     : ((const int*)yv)[base + tid];
        ysm[tid] = d;
        atomicAdd(&cnt[d], 1);
    }
    __syncthreads();

    float4 sa0 = {0,0,0,0}, sa1 = {0,0,0,0}, sa2 = {0,0,0,0}, sa3 = {0,0,0,0};
    float4 sa4 = {0,0,0,0}, sa5 = {0,0,0,0}, sa6 = {0,0,0,0}, sa7 = {0,0,0,0};
    float4 qa0 = {0,0,0,0}, qa1 = {0,0,0,0}, qa2 = {0,0,0,0}, qa3 = {0,0,0,0};
    float4 qa4 = {0,0,0,0}, qa5 = {0,0,0,0}, qa6 = {0,0,0,0}, qa7 = {0,0,0,0};

    const char* gsrc = (const char*)(x + (size_t)base * F4);
    const uint32_t ring0 = smem_u32(ring);
    const int nst = (nrows + TROWS - 1) / TROWS;

#define ISSUE(SLOT, ST) do { \
        int _rb = (ST) * TROWS; \
        uint32_t _bytes = (uint32_t)min(TROWS, nrows - _rb) * 4096u; \
        uint32_t _mb = smem_u32(&mbar_s[SLOT]); \
        mbar_expect_tx(_mb, _bytes); \
        if (_rb + TROWS <= cutr) \
            bulk_g2s_ef(ring0 + (SLOT) * STBYTES, gsrc + (size_t)(ST) * STBYTES, _bytes, _mb); \
        else \
            bulk_g2s   (ring0 + (SLOT) * STBYTES, gsrc + (size_t)(ST) * STBYTES, _bytes, _mb); \
    } while (0)

    // prologue: fill the ring
    if (tid == 0) {
        for (int s = 0; s < STAGES && s < nst; s++) ISSUE(s, s);
    }

    for (int i = 0; i < nst; i++) {
        const int slot = i % STAGES;
        const uint32_t mb = smem_u32(&mbar_s[slot]);
        mbar_wait(mb, (unsigned)(i / STAGES) & 1u);

        const int rows  = min(TROWS, nrows - i * TROWS);
        const int rbase = i * TROWS;
        const float4* bufp = ring + slot * (TROWS * 256) + tid;
        if (rows == TROWS) {
            #pragma unroll
            for (int j = 0; j < TROWS; j++) {
                float4 vv = bufp[j * 256];
                int d = ysm[rbase + j];
                ACC_SWITCH(d);
            }
        } else {
            for (int j = 0; j < rows; j++) {
                float4 vv = bufp[j * 256];
                int d = ysm[rbase + j];
                ACC_SWITCH(d);
            }
        }
        __syncthreads();                         // empty-barrier: all reads done
        const int nxt = i + STAGES;
        if (tid == 0 && nxt < nst) ISSUE(slot, nxt);
    }

    // partials: default policy -> L2-resident for table_k
    float4* psum = (float4*)(g_psum + (size_t)b * DOMS * F);
    float4* psq  = (float4*)(g_psq  + (size_t)b * DOMS * F);
    psum[0 * F4 + tid] = sa0; psq[0 * F4 + tid] = qa0;
    psum[1 * F4 + tid] = sa1; psq[1 * F4 + tid] = qa1;
    psum[2 * F4 + tid] = sa2; psq[2 * F4 + tid] = qa2;
    psum[3 * F4 + tid] = sa3; psq[3 * F4 + tid] = qa3;
    psum[4 * F4 + tid] = sa4; psq[4 * F4 + tid] = qa4;
    psum[5 * F4 + tid] = sa5; psq[5 * F4 + tid] = qa5;
    psum[6 * F4 + tid] = sa6; psq[6 * F4 + tid] = qa6;
    psum[7 * F4 + tid] = sa7; psq[7 * F4 + tid] = qa7;
    if (tid < DOMS) g_pcnt[b * DOMS + tid] = (nrows > 0) ? cnt[tid] : 0;
}

// ================= K2: distributed partial reduce -> (scale, bias) table =========
__global__ void __launch_bounds__(TPB, 2) table_k(
    const float* __restrict__ gamma, const float* __restrict__ beta)
{
    __shared__ int   scnt[DOMS], cpart[64];
    __shared__ float sred[9][28], qred[9][28];

    const int tid = threadIdx.x;
    const int b   = blockIdx.x;

    if (tid < 64) {
        int d = tid & 7, g = tid >> 3;
        int s0 = g * 37, s1 = min(NBLK, s0 + 37);
        int c = 0;
        for (int sl = s0; sl < s1; sl++) c += g_pcnt[sl * DOMS + d];
        cpart[tid] = c;
    }
    __syncthreads();
    if (tid < DOMS) {
        int c = 0;
        #pragma unroll
        for (int g = 0; g < 8; g++) c += cpart[g * 8 + tid];
        scnt[tid] = c;
    }

    const int start = b * 28;                   // 296*28 >= 8192
    const int p = tid % 28, c = tid / 28;       // c in 0..9 (c==9 idle)
    if (c < 9 && start + p < DOMS * F) {
        int j  = start + p;
        int s0 = c * 33, s1 = min(NBLK, s0 + 33);
        float ss = 0.f, qq = 0.f;
        for (int sl = s0; sl < s1; sl++) {
            ss += g_psum[(size_t)sl * (DOMS * F) + j];   // expect L2 hits
            qq += g_psq [(size_t)sl * (DOMS * F) + j];
        }
        sred[c][p] = ss; qred[c][p] = qq;
    }
    __syncthreads();
    if (tid < 28 && start + tid < DOMS * F) {
        int jj = start + tid;
        float ss = 0.f, qq = 0.f;
        #pragma unroll
        for (int cc = 0; cc < 9; cc++) { ss += sred[cc][tid]; qq += qred[cc][tid]; }
        int d = jj >> 10, f = jj & (F - 1);
        float cf = (float)scnt[d];
        float sc, bi;
        if (cf > 1.f) {
            float inv  = 1.f / cf;
            float mean = ss * inv;
            float var  = fmaxf(qq * inv - mean * mean, 0.f);
            sc = gamma[f] * rsqrtf(var + EPSV);
            bi = fmaf(-mean, sc, beta[f]);
        } else if (cf == 1.f) { sc = 1.f; bi = 0.f; }   // count==1 -> raw x
        else                  { sc = 0.f; bi = 0.f; }   // count==0 -> 0
        g_scale[jj] = sc;
        g_bias [jj] = bi;
    }
}

// ================= K3: normalize, pipelined descending stream (R11) ===============
__global__ void __launch_bounds__(TPB, 2) norm_k(
    const float4* __restrict__ x, const void* __restrict__ yv,
    float4* __restrict__ out, int n)
{
    __shared__ int ysm[RMAX];

    const int tid   = threadIdx.x;
    const int b     = blockIdx.x;
    const int rpb   = (n + NBLK - 1) / NBLK;
    const int base  = b * rpb;
    const int nrows = min(rpb, n - base);

    int is64 = detect_is64(yv, n, tid);

    if (tid < nrows)
        ysm[tid] = is64 ? (int)((const long long*)yv)[base + tid]
                        : ((const int*)yv)[base + tid];
    __syncthreads();

    const float4* sc4 = (const float4*)g_scale;
    const float4* bi4 = (const float4*)g_bias;
    const float4* xc  = x   + (size_t)base * F4 + tid;
    float4*       oc  = out + (size_t)base * F4 + tid;

    const int k = nrows >> 2;                       // full 4-row groups

    for (int r = nrows - 1; r >= k * 4; r--) {      // tail first (descending)
        int d = ysm[r];
        float4 v  = __ldcs(xc + (size_t)r * F4);
        float4 sc = sc4[d * F4 + tid];
        float4 bi = bi4[d * F4 + tid];
        float4 o;
        o.x = fmaf(v.x, sc.x, bi.x);
        o.y = fmaf(v.y, sc.y, bi.y);
        o.z = fmaf(v.z, sc.z, bi.z);
        o.w = fmaf(v.w, sc.w, bi.w);
        __stcs(oc + (size_t)r * F4, o);
    }

#define NLOAD(VB, DB, G) do { int _rr = (G) * 4; \
    _Pragma("unroll") for (int _i = 0; _i < 4; _i++) { \
        VB[_i] = __ldcs(xc + (size_t)(_rr + _i) * F4); DB[_i] = ysm[_rr + _i]; } } while (0)

#define NSTORE(VB, DB, G) do { int _rr = (G) * 4; \
    _Pragma("unroll") for (int _i = 0; _i < 4; _i++) { \
        float4 sc = sc4[DB[_i] * F4 + tid]; \
        float4 bi = bi4[DB[_i] * F4 + tid]; \
        float4 o; \
        o.x = fmaf(VB[_i].x, sc.x, bi.x); \
        o.y = fmaf(VB[_i].y, sc.y, bi.y); \
        o.z = fmaf(VB[_i].z, sc.z, bi.z); \
        o.w = fmaf(VB[_i].w, sc.w, bi.w); \
        __stcs(oc + (size_t)(_rr + _i) * F4, o); } } while (0)

    if (k > 0) {
        float4 vA[4], vB[4]; int dA[4], dB[4];
        NLOAD(vA, dA, k - 1);                       // prologue (highest group)
        int g = k - 2;
        for (; g >= 1; g -= 2) {                    // steady state: load-ahead
            NLOAD(vB, dB, g);
            NSTORE(vA, dA, g + 1);
            NLOAD(vA, dA, g - 1);
            NSTORE(vB, dB, g);
        }
        if (g == 0) {
            NLOAD(vB, dB, 0);
            NSTORE(vA, dA, 1);
            NSTORE(vB, dB, 0);
        } else {
            NSTORE(vA, dA, 0);
        }
    }
}

// ---------------- launch ----------------
extern "C" void kernel_launch(void* const* d_in, const int* in_sizes, int n_in,
                              void* d_out, int out_size) {
    const float4* x     = (const float4*)d_in[0];
    const void*   y     = d_in[1];
    const float*  gamma = (const float*)d_in[2];
    const float*  beta  = (const float*)d_in[3];
    float4*       out   = (float4*)d_out;

    int n = in_sizes[1];   // batch (y element count)

    static int smem_set = 0;
    if (!smem_set) {
        cudaFuncSetAttribute(stats_k, cudaFuncAttributeMaxDynamicSharedMemorySize,
                             STAGES * STBYTES);
        smem_set = 1;
    }
    stats_k<<<NBLK, TPB, STAGES * STBYTES>>>(x, y, n);
    table_k<<<NBLK, TPB>>>(gamma, beta);
    norm_k <<<NBLK, TPB>>>(x, y, out, n);
}